// round 1
// baseline (speedup 1.0000x reference)
#include <cuda_runtime.h>
#include <math.h>
#include <stdint.h>

// Problem dims (fixed by the dataset)
#define DT 512                 // time steps
#define DB 256                 // batch
#define DI 256                 // input dim
#define DH 256                 // hidden dim
#define DG 768                 // 3*H
#define DP (DT * DB)           // 131072 flat (t,b) positions

// ---------------- device scratch (static: no allocations allowed) ----------
__device__ int   g_src[DP];        // per packed position: flat x-row to gather (or -1)
__device__ int   g_order[DP];      // order[k] = flat index of k-th True of batch_mask (row-major)
__device__ int   g_len[DB];        // lengths per batch column
__device__ int   g_maxlen;
__device__ int   g_ntrue;
__device__ float g_h0[DB * DH];    // hidden ping-pong buffers
__device__ float g_h1[DB * DH];
__device__ float g_gi[(size_t)DP * DG];   // precomputed input projections (402 MB)

// ---------------------------------------------------------------------------
// Kernel 1: build lengths, packed mask, prefix ranks, order[], src[]
// Single CTA of 1024 threads; each thread owns a contiguous chunk of 128.
// mask is read as 32-bit words; nonzero bits == True (works for fp32 1.0/0.0
// and int32 1/0 encodings of the boolean mask).
// ---------------------------------------------------------------------------
__global__ void k_prep(const int* __restrict__ mask) {
    __shared__ int sLen[DB];
    __shared__ int sWm[32], sWp[32];
    __shared__ int sMax;
    const int tid = threadIdx.x;
    if (tid < DB) sLen[tid] = 0;
    if (tid == 0) sMax = 0;
    __syncthreads();

    { // column lengths: thread handles b = tid%256, t = tid/256 + 4k (coalesced)
        const int b = tid & 255;
        int acc = 0;
        for (int t = tid >> 8; t < DT; t += 4) acc += (mask[(t << 8) + b] != 0) ? 1 : 0;
        atomicAdd(&sLen[b], acc);
    }
    __syncthreads();
    if (tid < DB) { g_len[tid] = sLen[tid]; atomicMax(&sMax, sLen[tid]); }
    __syncthreads();
    if (tid == 0) g_maxlen = sMax;

    // chunk counts for both masks
    const int base = tid << 7;
    int cm = 0, cp = 0;
    #pragma unroll 4
    for (int i = 0; i < 128; i++) {
        const int p = base + i;
        cm += (mask[p] != 0) ? 1 : 0;
        cp += ((p >> 8) < sLen[p & 255]) ? 1 : 0;
    }
    // two-level exclusive scan over the 1024 chunk counts
    const int lane = tid & 31, wid = tid >> 5;
    int im = cm, ip = cp;
    #pragma unroll
    for (int d = 1; d < 32; d <<= 1) {
        const int um = __shfl_up_sync(0xffffffffu, im, d);
        const int up = __shfl_up_sync(0xffffffffu, ip, d);
        if (lane >= d) { im += um; ip += up; }
    }
    if (lane == 31) { sWm[wid] = im; sWp[wid] = ip; }
    __syncthreads();
    if (wid == 0) {
        const int am = sWm[lane], ap = sWp[lane];
        int jm = am, jp = ap;
        #pragma unroll
        for (int d = 1; d < 32; d <<= 1) {
            const int um = __shfl_up_sync(0xffffffffu, jm, d);
            const int up = __shfl_up_sync(0xffffffffu, jp, d);
            if (lane >= d) { jm += um; jp += up; }
        }
        sWm[lane] = jm - am;   // exclusive per-warp offsets
        sWp[lane] = jp - ap;
        if (lane == 31) g_ntrue = jm;
    }
    __syncthreads();

    int mrank = sWm[wid] + im - cm;   // exclusive rank at chunk start
    int prank = sWp[wid] + ip - cp;
    for (int i = 0; i < 128; i++) {
        const int p  = base + i;
        const int mt = (mask[p] != 0) ? 1 : 0;
        const int pt = ((p >> 8) < sLen[p & 255]) ? 1 : 0;
        if (mt) g_order[mrank] = p;
        g_src[p] = pt ? prank : -1;   // temporarily store prank
        mrank += mt; prank += pt;
    }
    __syncthreads();                  // block-wide visibility of g_order / g_src
    for (int i = 0; i < 128; i++) {
        const int p = base + i;
        const int k = g_src[p];
        if (k >= 0) g_src[p] = g_order[k];   // resolve: x-row to gather
    }
}

// ---------------------------------------------------------------------------
// Kernel 2: gi = gather(x) @ W_ih^T + b_ih  for all packed-valid rows.
// 64x64x16 fp32 SIMT tile, 256 threads, 4x4 register tile. Tiles with no
// valid row return immediately (halves the work on average).
// ---------------------------------------------------------------------------
__global__ void k_gi(const float* __restrict__ x,
                     const float* __restrict__ Wih,
                     const float* __restrict__ bih) {
    __shared__ float As[16][64];
    __shared__ float Bs[16][64];
    __shared__ int   sSrc[64];
    __shared__ int   sAny;
    const int tid = threadIdx.x;
    const int gt = blockIdx.x;     // 12 tiles over G=768
    const int pt = blockIdx.y;     // 2048 tiles over P

    if (tid == 0) sAny = 0;
    __syncthreads();
    if (tid < 64) {
        const int s = g_src[(pt << 6) + tid];
        sSrc[tid] = (s >= 0) ? s : 0;
        if (s >= 0) sAny = 1;   // benign race: everyone writes 1
    }
    __syncthreads();
    if (!sAny) return;

    float acc[4][4];
    #pragma unroll
    for (int i = 0; i < 4; i++)
        #pragma unroll
        for (int j = 0; j < 4; j++) acc[i][j] = 0.f;

    const int tm = tid & 15, tn = tid >> 4;     // output micro-tile coords
    const int m  = tid >> 2;                    // load row 0..63
    const int kk = (tid & 3) << 2;              // load k offset 0/4/8/12
    const float* xrow = x   + ((size_t)sSrc[m] << 8);
    const float* wrow = Wih + ((size_t)((gt << 6) + m) << 8);

    for (int k0 = 0; k0 < DI; k0 += 16) {
        const float4 av = *(const float4*)(xrow + k0 + kk);
        const float4 bv = *(const float4*)(wrow + k0 + kk);
        As[kk + 0][m] = av.x; As[kk + 1][m] = av.y; As[kk + 2][m] = av.z; As[kk + 3][m] = av.w;
        Bs[kk + 0][m] = bv.x; Bs[kk + 1][m] = bv.y; Bs[kk + 2][m] = bv.z; Bs[kk + 3][m] = bv.w;
        __syncthreads();
        #pragma unroll
        for (int k = 0; k < 16; k++) {
            const float4 a = *(const float4*)&As[k][tm << 2];
            const float4 b = *(const float4*)&Bs[k][tn << 2];
            acc[0][0] += a.x * b.x; acc[0][1] += a.x * b.y; acc[0][2] += a.x * b.z; acc[0][3] += a.x * b.w;
            acc[1][0] += a.y * b.x; acc[1][1] += a.y * b.y; acc[1][2] += a.y * b.z; acc[1][3] += a.y * b.w;
            acc[2][0] += a.z * b.x; acc[2][1] += a.z * b.y; acc[2][2] += a.z * b.z; acc[2][3] += a.z * b.w;
            acc[3][0] += a.w * b.x; acc[3][1] += a.w * b.y; acc[3][2] += a.w * b.z; acc[3][3] += a.w * b.w;
        }
        __syncthreads();
    }

    const float4 bias = *(const float4*)(bih + (gt << 6) + (tn << 2));
    const size_t gbase = (size_t)((pt << 6) + (tm << 2)) * DG + (gt << 6) + (tn << 2);
    #pragma unroll
    for (int i = 0; i < 4; i++) {
        float4 o;
        o.x = acc[i][0] + bias.x; o.y = acc[i][1] + bias.y;
        o.z = acc[i][2] + bias.z; o.w = acc[i][3] + bias.w;
        *(float4*)(g_gi + gbase + (size_t)i * DG) = o;
    }
}

// ---------------------------------------------------------------------------
// Kernel 3: one GRU step. Grid (16 j-tiles, 16 b-tiles), 128 threads.
// Each CTA: 16 j x 16 b outputs, 3 gates, K=256 -> 196k FMA.
// Skips entirely once t >= maxlen (h frozen; no output rows remain).
// Scatters its output row directly to d_out via g_order.
// ---------------------------------------------------------------------------
__global__ void k_step(const int t,
                       const float* __restrict__ Whh,
                       const float* __restrict__ bhh,
                       float* __restrict__ out, const size_t out_elems) {
    if (t >= g_maxlen) return;
    const float* __restrict__ hin  = (t & 1) ? g_h1 : g_h0;
    float* __restrict__       hout = (t & 1) ? g_h0 : g_h1;

    __shared__ float sW[3][16][68];   // 3 gates x 16 j-rows x 64 k (pad 4)
    __shared__ float sh[16][68];      // 16 b-rows x 64 k
    const int tid = threadIdx.x;
    const int jt = blockIdx.x;        // j tile: j in [jt*16, jt*16+16)
    const int bt = blockIdx.y;        // b tile
    const int jj = tid & 7;           // handles j = jt*16 + jj and +8
    const int bb = tid >> 3;          // 0..15

    float acc[3][2] = {{0.f, 0.f}, {0.f, 0.f}, {0.f, 0.f}};

    for (int k0 = 0; k0 < DH; k0 += 64) {
        #pragma unroll
        for (int it = 0; it < 6; it++) {        // W slice: 48 rows x 16 float4
            const int lin  = tid + (it << 7);
            const int r    = lin >> 4;          // 0..47
            const int kq   = (lin & 15) << 2;
            const int gate = r >> 4, jr = r & 15;
            const float4 v = *(const float4*)(Whh +
                ((size_t)((gate << 8) + (jt << 4) + jr) << 8) + k0 + kq);
            *(float4*)&sW[gate][jr][kq] = v;
        }
        #pragma unroll
        for (int it = 0; it < 2; it++) {        // h slice: 16 rows x 16 float4
            const int lin = tid + (it << 7);
            const int r   = lin >> 4;
            const int kq  = (lin & 15) << 2;
            const float4 v = *(const float4*)(hin + ((size_t)((bt << 4) + r) << 8) + k0 + kq);
            *(float4*)&sh[r][kq] = v;
        }
        __syncthreads();
        #pragma unroll
        for (int k = 0; k < 64; k += 4) {
            const float4 hv = *(const float4*)&sh[bb][k];
            #pragma unroll
            for (int g = 0; g < 3; g++) {
                #pragma unroll
                for (int d = 0; d < 2; d++) {
                    const float4 wv = *(const float4*)&sW[g][jj + (d << 3)][k];
                    acc[g][d] += hv.x * wv.x + hv.y * wv.y + hv.z * wv.z + hv.w * wv.w;
                }
            }
        }
        __syncthreads();
    }

    const int b     = (bt << 4) + bb;
    const int valid = (t < g_len[b]) ? 1 : 0;
    const int nflat = (t << 8) + b;
    const int dest  = (nflat < g_ntrue) ? g_order[nflat] : -1;
    const size_t pgi = (size_t)nflat * DG;

    #pragma unroll
    for (int d = 0; d < 2; d++) {
        const int j = (jt << 4) + jj + (d << 3);
        const float hold = hin[((size_t)b << 8) + j];
        float hn;
        if (valid) {
            const float gir = g_gi[pgi + j];
            const float giz = g_gi[pgi + 256 + j];
            const float gin = g_gi[pgi + 512 + j];
            const float ghr = acc[0][d] + bhh[j];
            const float ghz = acc[1][d] + bhh[256 + j];
            const float ghn = acc[2][d] + bhh[512 + j];
            const float r = 1.f / (1.f + expf(-(gir + ghr)));
            const float z = 1.f / (1.f + expf(-(giz + ghz)));
            const float n = tanhf(gin + r * ghn);
            hn = (1.f - z) * n + z * hold;
        } else {
            hn = hold;
        }
        hout[((size_t)b << 8) + j] = hn;
        if (dest >= 0) {
            const size_t o = ((size_t)dest << 8) + j;
            if (o < out_elems) out[o] = valid ? hn : 0.f;
        }
    }
}

// ---------------------------------------------------------------------------
// Small helpers
// ---------------------------------------------------------------------------
__global__ void k_zero(float* __restrict__ out, const size_t n) {
    size_t i = (size_t)blockIdx.x * blockDim.x + threadIdx.x;
    const size_t stride = (size_t)gridDim.x * blockDim.x;
    for (; i < n; i += stride) out[i] = 0.f;
}

__global__ void k_init(const float* __restrict__ hx) {
    const int i = blockIdx.x * blockDim.x + threadIdx.x;
    if (i < DB * DH) g_h0[i] = hx[i];
}

__global__ void k_fin(float* __restrict__ out, const size_t out_elems) {
    // final h lives in buffer (maxlen & 1) thanks to the ping-pong + early-exit
    const float* h = (g_maxlen & 1) ? g_h1 : g_h0;
    const int i = blockIdx.x * blockDim.x + threadIdx.x;
    if (i < DB * DH) {
        const size_t o = (size_t)DP * DH + i;
        if (o < out_elems) out[o] = h[i];
    }
}

// ---------------------------------------------------------------------------
extern "C" void kernel_launch(void* const* d_in, const int* in_sizes, int n_in,
                              void* d_out, int out_size) {
    const float* x    = (const float*)d_in[0];   // [T,B,IN]
    const float* hx   = (const float*)d_in[1];   // [1,B,H]
    const int*   mask = (const int*)  d_in[2];   // [T,B]  (bit-nonzero == True)
    const float* Wih  = (const float*)d_in[3];   // [3H,IN]
    const float* Whh  = (const float*)d_in[4];   // [3H,H]
    const float* bih  = (const float*)d_in[5];   // [3H]
    const float* bhh  = (const float*)d_in[6];   // [3H]
    float* out = (float*)d_out;
    const size_t oe = (size_t)out_size;

    k_prep<<<1, 1024>>>(mask);
    k_zero<<<2048, 256>>>(out, oe);
    k_init<<<64, 1024>>>(hx);
    k_gi<<<dim3(12, 2048), 256>>>(x, Wih, bih);
    for (int t = 0; t < DT; ++t) {
        k_step<<<dim3(16, 16), 128>>>(t, Whh, bhh, out, oe);
    }
    k_fin<<<64, 1024>>>(out, oe);
}

// round 2
// speedup vs baseline: 1.1473x; 1.1473x over previous
#include <cuda_runtime.h>
#include <math.h>
#include <stdint.h>

// Problem dims (fixed by the dataset)
#define DT 512
#define DB 256
#define DI 256
#define DH 256
#define DG 768
#define DP (DT * DB)

typedef unsigned long long u64;

// ---------------- device scratch ----------
__device__ int   g_src[DP];
__device__ int   g_order[DP];
__device__ int   g_len[DB];
__device__ int   g_maxlen;
__device__ int   g_ntrue;
__device__ float g_gi[(size_t)DP * DG];

// ---------------- f32x2 helpers (sm_103a packed fp32) ----------
__device__ __forceinline__ u64 pack2(float lo, float hi) {
    u64 r; asm("mov.b64 %0, {%1, %2};" : "=l"(r) : "f"(lo), "f"(hi)); return r;
}
__device__ __forceinline__ void unpack2(u64 v, float& lo, float& hi) {
    asm("mov.b64 {%0, %1}, %2;" : "=f"(lo), "=f"(hi) : "l"(v));
}
__device__ __forceinline__ void fma2(u64& d, u64 a, u64 b) {
    asm("fma.rn.f32x2 %0, %1, %2, %0;" : "+l"(d) : "l"(a), "l"(b));
}

// ---------------------------------------------------------------------------
// Kernel 1: lengths, packed mask, ranks, order[], src[]  (1 CTA, 1024 thr)
// ---------------------------------------------------------------------------
__global__ void k_prep(const int* __restrict__ mask) {
    __shared__ int sLen[DB];
    __shared__ int sWm[32], sWp[32];
    __shared__ int sMax;
    const int tid = threadIdx.x;
    if (tid < DB) sLen[tid] = 0;
    if (tid == 0) sMax = 0;
    __syncthreads();

    {
        const int b = tid & 255;
        int acc = 0;
        for (int t = tid >> 8; t < DT; t += 4) acc += (mask[(t << 8) + b] != 0) ? 1 : 0;
        atomicAdd(&sLen[b], acc);
    }
    __syncthreads();
    if (tid < DB) { g_len[tid] = sLen[tid]; atomicMax(&sMax, sLen[tid]); }
    __syncthreads();
    if (tid == 0) g_maxlen = sMax;

    const int base = tid << 7;
    int cm = 0, cp = 0;
    #pragma unroll 4
    for (int i = 0; i < 128; i++) {
        const int p = base + i;
        cm += (mask[p] != 0) ? 1 : 0;
        cp += ((p >> 8) < sLen[p & 255]) ? 1 : 0;
    }
    const int lane = tid & 31, wid = tid >> 5;
    int im = cm, ip = cp;
    #pragma unroll
    for (int d = 1; d < 32; d <<= 1) {
        const int um = __shfl_up_sync(0xffffffffu, im, d);
        const int up = __shfl_up_sync(0xffffffffu, ip, d);
        if (lane >= d) { im += um; ip += up; }
    }
    if (lane == 31) { sWm[wid] = im; sWp[wid] = ip; }
    __syncthreads();
    if (wid == 0) {
        const int am = sWm[lane], ap = sWp[lane];
        int jm = am, jp = ap;
        #pragma unroll
        for (int d = 1; d < 32; d <<= 1) {
            const int um = __shfl_up_sync(0xffffffffu, jm, d);
            const int up = __shfl_up_sync(0xffffffffu, jp, d);
            if (lane >= d) { jm += um; jp += up; }
        }
        sWm[lane] = jm - am;
        sWp[lane] = jp - ap;
        if (lane == 31) g_ntrue = jm;
    }
    __syncthreads();

    int mrank = sWm[wid] + im - cm;
    int prank = sWp[wid] + ip - cp;
    for (int i = 0; i < 128; i++) {
        const int p  = base + i;
        const int mt = (mask[p] != 0) ? 1 : 0;
        const int pt = ((p >> 8) < sLen[p & 255]) ? 1 : 0;
        if (mt) g_order[mrank] = p;
        g_src[p] = pt ? prank : -1;
        mrank += mt; prank += pt;
    }
    __syncthreads();
    for (int i = 0; i < 128; i++) {
        const int p = base + i;
        const int k = g_src[p];
        if (k >= 0) g_src[p] = g_order[k];
    }
}

// ---------------------------------------------------------------------------
// Kernel 2: gi = gather(x) @ W_ih^T + b_ih. 64x64x16 tile, f32x2 inner loop.
// ---------------------------------------------------------------------------
__global__ void k_gi(const float* __restrict__ x,
                     const float* __restrict__ Wih,
                     const float* __restrict__ bih) {
    __shared__ float As[16][64];
    __shared__ float Bs[16][64];
    __shared__ int   sSrc[64];
    __shared__ int   sAny;
    const int tid = threadIdx.x;
    const int gt = blockIdx.x;
    const int pt = blockIdx.y;

    if (tid == 0) sAny = 0;
    __syncthreads();
    if (tid < 64) {
        const int s = g_src[(pt << 6) + tid];
        sSrc[tid] = (s >= 0) ? s : 0;
        if (s >= 0) sAny = 1;
    }
    __syncthreads();
    if (!sAny) return;

    u64 acc[4][2] = {{0ull, 0ull}, {0ull, 0ull}, {0ull, 0ull}, {0ull, 0ull}};

    const int tm = tid & 15, tn = tid >> 4;
    const int m  = tid >> 2;
    const int kk = (tid & 3) << 2;
    const float* xrow = x   + ((size_t)sSrc[m] << 8);
    const float* wrow = Wih + ((size_t)((gt << 6) + m) << 8);

    for (int k0 = 0; k0 < DI; k0 += 16) {
        const float4 av = *(const float4*)(xrow + k0 + kk);
        const float4 bv = *(const float4*)(wrow + k0 + kk);
        As[kk + 0][m] = av.x; As[kk + 1][m] = av.y; As[kk + 2][m] = av.z; As[kk + 3][m] = av.w;
        Bs[kk + 0][m] = bv.x; Bs[kk + 1][m] = bv.y; Bs[kk + 2][m] = bv.z; Bs[kk + 3][m] = bv.w;
        __syncthreads();
        #pragma unroll
        for (int k = 0; k < 16; k++) {
            const float4  a  = *(const float4*)&As[k][tm << 2];
            const double2 bd = *(const double2*)&Bs[k][tn << 2];
            const u64 b0 = __double_as_longlong(bd.x);
            const u64 b1 = __double_as_longlong(bd.y);
            const u64 a0 = pack2(a.x, a.x), a1 = pack2(a.y, a.y);
            const u64 a2 = pack2(a.z, a.z), a3 = pack2(a.w, a.w);
            fma2(acc[0][0], a0, b0); fma2(acc[0][1], a0, b1);
            fma2(acc[1][0], a1, b0); fma2(acc[1][1], a1, b1);
            fma2(acc[2][0], a2, b0); fma2(acc[2][1], a2, b1);
            fma2(acc[3][0], a3, b0); fma2(acc[3][1], a3, b1);
        }
        __syncthreads();
    }

    const float4 bias = *(const float4*)(bih + (gt << 6) + (tn << 2));
    const size_t gbase = (size_t)((pt << 6) + (tm << 2)) * DG + (gt << 6) + (tn << 2);
    #pragma unroll
    for (int i = 0; i < 4; i++) {
        float4 o;
        unpack2(acc[i][0], o.x, o.y);
        unpack2(acc[i][1], o.z, o.w);
        o.x += bias.x; o.y += bias.y; o.z += bias.z; o.w += bias.w;
        *(float4*)(g_gi + gbase + (size_t)i * DG) = o;
    }
}

// ---------------------------------------------------------------------------
// Kernel 3: persistent cluster recurrence. 16 clusters x 8 CTAs, 256 thr.
// Each CTA: W_hh slice (32 j x 3 gates) resident in smem all steps; cluster
// shares h via DSMEM broadcast + barrier.cluster once per step.
// ---------------------------------------------------------------------------
#define CSZ 8            // CTAs per cluster
#define BPC 16           // batch columns per cluster
#define WK  520          // floats per (j-pair, gate) row: 256 k-pairs + pad
#define HROW 260         // floats per h row (256 + pad)
#define WOFF 0
#define HOFF0 (48 * WK)               // 24960
#define HOFF1 (HOFF0 + BPC * HROW)    // 29120
#define SMEM_F (HOFF1 + BPC * HROW)   // 33280 floats = 133120 B

extern __shared__ float s_rec[];

__global__ void __cluster_dims__(CSZ, 1, 1) __launch_bounds__(256, 1)
k_rec(const float* __restrict__ Whh, const float* __restrict__ bhh,
      const float* __restrict__ hx, float* __restrict__ out, const size_t oe) {
    const int tid = threadIdx.x;
    uint32_t rank; asm("mov.u32 %0, %%cluster_ctarank;" : "=r"(rank));
    const int clu = blockIdx.x / CSZ;
    const int b0  = clu * BPC;

    uint32_t sbase;
    asm("{ .reg .u64 t; cvta.to.shared.u64 t, %1; cvt.u32.u64 %0, t; }"
        : "=r"(sbase) : "l"(s_rec));

    // --- load resident W slice: rows g*256 + rank*32 + jj, j-pair interleaved
    float* Ws = s_rec + WOFF;
    for (int idx = tid; idx < 96 * 64; idx += 256) {
        const int row = idx >> 6;            // 0..95 = g*32 + jj
        const int g = row >> 5, jj = row & 31;
        const int kq = (idx & 63) << 2;
        const float4 v = *(const float4*)(Whh +
            ((size_t)((g << 8) + ((int)rank << 5) + jj) << 8) + kq);
        float* dst = Ws + (size_t)((jj >> 1) * 3 + g) * WK + (jj & 1);
        dst[(kq + 0) << 1] = v.x; dst[(kq + 1) << 1] = v.y;
        dst[(kq + 2) << 1] = v.z; dst[(kq + 3) << 1] = v.w;
    }
    // --- load initial h for our 16 batch columns
    for (int idx = tid; idx < BPC * 64; idx += 256) {
        const int b = idx >> 6; const int kq = (idx & 63) << 2;
        const float4 v = *(const float4*)(hx + ((size_t)(b0 + b) << 8) + kq);
        *(float4*)&s_rec[HOFF0 + b * HROW + kq] = v;
    }

    int lmax = 0;
    #pragma unroll
    for (int i = 0; i < BPC; i++) lmax = max(lmax, g_len[b0 + i]);

    const int w = tid >> 5, lane = tid & 31;
    const int jl = lane & 1, bloc = lane >> 1;
    const int jp = (w << 1) + jl;            // local j-pair 0..15
    const int Jg = ((int)rank << 5) + (jp << 1);  // global even j
    const int bg = b0 + bloc;
    const int blen = g_len[bg];
    const int ntrue = g_ntrue;

    const float2 bh_r = *(const float2*)(bhh + Jg);
    const float2 bh_z = *(const float2*)(bhh + 256 + Jg);
    const float2 bh_n = *(const float2*)(bhh + 512 + Jg);
    const float* wbase = Ws + (size_t)(jp * 3) * WK;   // gate stride WK

    asm volatile("barrier.cluster.arrive.aligned;" ::: "memory");
    asm volatile("barrier.cluster.wait.aligned;"   ::: "memory");

    for (int t = 0; t < lmax; t++) {
        const int cur = t & 1;
        const float* hc = s_rec + (cur ? HOFF1 : HOFF0);
        const uint32_t hn_off = cur ? HOFF0 : HOFF1;
        const int nflat = (t << 8) + bg;

        // prefetch (consumed after the long k-loop)
        const float2 gi_r = __ldg((const float2*)(g_gi + (size_t)nflat * DG + Jg));
        const float2 gi_z = __ldg((const float2*)(g_gi + (size_t)nflat * DG + 256 + Jg));
        const float2 gi_n = __ldg((const float2*)(g_gi + (size_t)nflat * DG + 512 + Jg));
        int dest = -1;
        if ((t < blen) && (nflat < ntrue)) dest = __ldg(&g_order[nflat]);
        const float2 hold = *(const float2*)&hc[bloc * HROW + Jg];

        u64 ar = 0ull, az = 0ull, an = 0ull;
        const float* hrow = &hc[bloc * HROW];
        #pragma unroll 4
        for (int k = 0; k < DH; k += 4) {
            const float4 hv = *(const float4*)&hrow[k];
            const u64 h0 = pack2(hv.x, hv.x), h1 = pack2(hv.y, hv.y);
            const u64 h2 = pack2(hv.z, hv.z), h3 = pack2(hv.w, hv.w);
            const double2 wr0 = *(const double2*)(wbase + 0 * WK + (k << 1));
            const double2 wr1 = *(const double2*)(wbase + 0 * WK + (k << 1) + 4);
            const double2 wz0 = *(const double2*)(wbase + 1 * WK + (k << 1));
            const double2 wz1 = *(const double2*)(wbase + 1 * WK + (k << 1) + 4);
            const double2 wn0 = *(const double2*)(wbase + 2 * WK + (k << 1));
            const double2 wn1 = *(const double2*)(wbase + 2 * WK + (k << 1) + 4);
            fma2(ar, h0, __double_as_longlong(wr0.x));
            fma2(ar, h1, __double_as_longlong(wr0.y));
            fma2(ar, h2, __double_as_longlong(wr1.x));
            fma2(ar, h3, __double_as_longlong(wr1.y));
            fma2(az, h0, __double_as_longlong(wz0.x));
            fma2(az, h1, __double_as_longlong(wz0.y));
            fma2(az, h2, __double_as_longlong(wz1.x));
            fma2(az, h3, __double_as_longlong(wz1.y));
            fma2(an, h0, __double_as_longlong(wn0.x));
            fma2(an, h1, __double_as_longlong(wn0.y));
            fma2(an, h2, __double_as_longlong(wn1.x));
            fma2(an, h3, __double_as_longlong(wn1.y));
        }

        float ghr0, ghr1, ghz0, ghz1, ghn0, ghn1;
        unpack2(ar, ghr0, ghr1);
        unpack2(az, ghz0, ghz1);
        unpack2(an, ghn0, ghn1);

        float hn0, hn1;
        {
            const float r0 = 1.f / (1.f + __expf(-(gi_r.x + ghr0 + bh_r.x)));
            const float z0 = 1.f / (1.f + __expf(-(gi_z.x + ghz0 + bh_z.x)));
            const float n0 = tanhf(gi_n.x + r0 * (ghn0 + bh_n.x));
            hn0 = (1.f - z0) * n0 + z0 * hold.x;
            const float r1 = 1.f / (1.f + __expf(-(gi_r.y + ghr1 + bh_r.y)));
            const float z1 = 1.f / (1.f + __expf(-(gi_z.y + ghz1 + bh_z.y)));
            const float n1 = tanhf(gi_n.y + r1 * (ghn1 + bh_n.y));
            hn1 = (1.f - z1) * n1 + z1 * hold.y;
        }
        if (t >= blen) { hn0 = hold.x; hn1 = hold.y; }

        // broadcast (b, Jg..Jg+1) into every CTA's next h buffer
        const u64 pk = pack2(hn0, hn1);
        const uint32_t daddr = sbase + ((hn_off + bloc * HROW + Jg) << 2);
        #pragma unroll
        for (int r2 = 0; r2 < CSZ; r2++) {
            uint32_t rem;
            asm("mapa.shared::cluster.u32 %0, %1, %2;" : "=r"(rem) : "r"(daddr), "r"(r2));
            asm volatile("st.shared::cluster.b64 [%0], %1;" :: "r"(rem), "l"(pk) : "memory");
        }

        if (dest >= 0) {
            const size_t o = ((size_t)dest << 8) + Jg;
            if (o + 1 < oe) *(float2*)(out + o) = make_float2(hn0, hn1);
        }

        asm volatile("barrier.cluster.arrive.aligned;" ::: "memory");
        asm volatile("barrier.cluster.wait.aligned;"   ::: "memory");
    }

    // final hidden state -> out[DP*H + b*H + j]
    const float* hf = s_rec + ((lmax & 1) ? HOFF1 : HOFF0);
    const float2 hv = *(const float2*)&hf[bloc * HROW + Jg];
    const size_t o = ((size_t)DP << 8) + ((size_t)bg << 8) + Jg;
    if (o + 1 < oe) *(float2*)(out + o) = hv;
}

// ---------------------------------------------------------------------------
__global__ void k_zero(float* __restrict__ out, const size_t n) {
    size_t i = (size_t)blockIdx.x * blockDim.x + threadIdx.x;
    const size_t stride = (size_t)gridDim.x * blockDim.x;
    for (; i < n; i += stride) out[i] = 0.f;
}

// ---------------------------------------------------------------------------
extern "C" void kernel_launch(void* const* d_in, const int* in_sizes, int n_in,
                              void* d_out, int out_size) {
    const float* x    = (const float*)d_in[0];
    const float* hx   = (const float*)d_in[1];
    const int*   mask = (const int*)  d_in[2];
    const float* Wih  = (const float*)d_in[3];
    const float* Whh  = (const float*)d_in[4];
    const float* bih  = (const float*)d_in[5];
    const float* bhh  = (const float*)d_in[6];
    float* out = (float*)d_out;
    const size_t oe = (size_t)out_size;

    static int s_attr_done = 0;
    if (!s_attr_done) {
        cudaFuncSetAttribute(k_rec, cudaFuncAttributeMaxDynamicSharedMemorySize,
                             SMEM_F * 4);
        s_attr_done = 1;
    }

    k_prep<<<1, 1024>>>(mask);
    k_zero<<<2048, 256>>>(out, oe);
    k_gi<<<dim3(12, 2048), 256>>>(x, Wih, bih);
    k_rec<<<128, 256, SMEM_F * 4>>>(Whh, bhh, hx, out, oe);
}